// round 6
// baseline (speedup 1.0000x reference)
#include <cuda_runtime.h>
#include <cuda_bf16.h>
#include <cstdint>

// Problem constants
#define QLEN 1024
#define MLEN 1024
#define KLEN 2048   // QLEN + MLEN
#define BSZ  4
#define NH   8
#define DH   64
#define DM   512    // NH*DH
#define SCALE 0.125f
#define LN_EPS 1e-5f

// ---------------------------------------------------------------------------
// Scratch (device globals; allocation inside kernel_launch is forbidden)
// ---------------------------------------------------------------------------
__device__ float g_kv [ (size_t)KLEN * BSZ * 2 * DM ];  // [klen*bsz, 1024] (k | v)
__device__ float g_q  [ (size_t)QLEN * BSZ * DM ];      // [qlen*bsz, 512]
__device__ float g_rk [ (size_t)KLEN * DM ];            // [klen, 512]
__device__ float g_vec[ (size_t)QLEN * BSZ * DM ];      // attn_vec
__device__ float g_ao [ (size_t)QLEN * BSZ * DM ];      // attn_out

// ---------------------------------------------------------------------------
// SGEMM: C[M,N] = A[M,K] @ B[K,N], row-major, fp32.
// BM=128, BN=64, BK=16, 256 threads, 8x4 per-thread microtile.
// Requires M%128==0, N%64==0, K%16==0 (true for all uses here).
// ---------------------------------------------------------------------------
#define BM 128
#define BN 64
#define BKK 16

__global__ __launch_bounds__(256) void sgemm_k(
    const float* __restrict__ A, const float* __restrict__ B,
    float* __restrict__ C, int M, int N, int K)
{
    __shared__ float As[BKK][BM + 4];
    __shared__ float Bs[BKK][BN + 4];

    const int tid = threadIdx.x;
    const int tx = tid & 15;
    const int ty = tid >> 4;
    const int m0 = blockIdx.y * BM;
    const int n0 = blockIdx.x * BN;

    const int arow = tid >> 2;        // 0..63
    const int akg  = (tid & 3) * 4;   // 0,4,8,12
    const int brow = tid >> 4;        // 0..15
    const int bcol = (tid & 15) * 4;

    float acc[8][4];
#pragma unroll
    for (int i = 0; i < 8; i++)
#pragma unroll
        for (int j = 0; j < 4; j++) acc[i][j] = 0.f;

    for (int k0 = 0; k0 < K; k0 += BKK) {
        // load A tile (transposed into As[k][m])
#pragma unroll
        for (int r = 0; r < 2; r++) {
            int m = arow + r * 64;
            float4 v = *(const float4*)(A + (size_t)(m0 + m) * K + k0 + akg);
            As[akg + 0][m] = v.x;
            As[akg + 1][m] = v.y;
            As[akg + 2][m] = v.z;
            As[akg + 3][m] = v.w;
        }
        // load B tile
        {
            float4 v = *(const float4*)(B + (size_t)(k0 + brow) * N + n0 + bcol);
            *(float4*)&Bs[brow][bcol] = v;
        }
        __syncthreads();

#pragma unroll
        for (int k = 0; k < BKK; k++) {
            float4 a0 = *(float4*)&As[k][ty * 8];
            float4 a1 = *(float4*)&As[k][ty * 8 + 4];
            float4 bb = *(float4*)&Bs[k][tx * 4];
            float av[8] = {a0.x, a0.y, a0.z, a0.w, a1.x, a1.y, a1.z, a1.w};
            float bv[4] = {bb.x, bb.y, bb.z, bb.w};
#pragma unroll
            for (int i = 0; i < 8; i++)
#pragma unroll
                for (int j = 0; j < 4; j++)
                    acc[i][j] += av[i] * bv[j];
        }
        __syncthreads();
    }

#pragma unroll
    for (int i = 0; i < 8; i++) {
        float4 v = make_float4(acc[i][0], acc[i][1], acc[i][2], acc[i][3]);
        *(float4*)(C + (size_t)(m0 + ty * 8 + i) * N + n0 + tx * 4) = v;
    }
}

// ---------------------------------------------------------------------------
// Fused flash attention with Transformer-XL relative bias.
//   score[i,j] = ( (q_i + rwb) . k_j  +  (q_i + rrb) . rk[j - i + QLEN-1] ) * SCALE
//   masked where j > i + MLEN; online softmax; accumulate P@V.
// Grid: (QLEN/64, BSZ*NH). Block: 256 threads (16x16), 4x4 microtile.
// Dynamic smem: 103680 bytes.
// ---------------------------------------------------------------------------
#define ATTN_SMEM_FLOATS (4*64*68 + 64*132 + 64)
#define ATTN_SMEM_BYTES  (ATTN_SMEM_FLOATS * 4)

__global__ __launch_bounds__(256) void attn_kernel(
    const float* __restrict__ qb,    // [qlen*bsz, 512]
    const float* __restrict__ kvb,   // [klen*bsz, 1024]
    const float* __restrict__ rkb,   // [klen, 512]
    const float* __restrict__ rwb,   // [8,64]
    const float* __restrict__ rrb,   // [8,64]
    float* __restrict__ vec)         // [qlen*bsz, 512]
{
    extern __shared__ float sh[];
    float* sh_q    = sh;                    // [k][i]  64 x 68  (q + rwb, transposed)
    float* sh_k    = sh_q  + 64 * 68;       // [k][j]  64 x 68
    float* sh_rk   = sh_k  + 64 * 68;       // [k][rr] 64 x 132 (128-row window)
    float* sh_v    = sh_rk + 64 * 132;      // [j][d]  64 x 68
    float* sh_p    = sh_v  + 64 * 68;       // [j][i]  64 x 68
    float* sh_diff = sh_p  + 64 * 68;       // [64] = rrb - rwb

    const int tid = threadIdx.x;
    const int tx = tid & 15;
    const int ty = tid >> 4;
    const int bn = blockIdx.y;
    const int b = bn >> 3;
    const int n = bn & 7;
    const int i0 = blockIdx.x * 64;
    const int iw = ty * 4;   // local i base
    const int jc = tx * 4;   // local j base (also out-dim base in PV)

    // Load q tile (+ r_w_bias), transposed to [k][i]
    for (int idx = tid; idx < 64 * 64; idx += 256) {
        int ii = idx >> 6, k = idx & 63;
        float qv = qb[(size_t)((i0 + ii) * BSZ + b) * DM + n * DH + k] + rwb[n * DH + k];
        sh_q[k * 68 + ii] = qv;
    }
    if (tid < 64) sh_diff[tid] = rrb[n * DH + tid] - rwb[n * DH + tid];

    float m[4], l[4], o[4][4];
#pragma unroll
    for (int i = 0; i < 4; i++) {
        m[i] = -1e30f; l[i] = 0.f;
#pragma unroll
        for (int j = 0; j < 4; j++) o[i][j] = 0.f;
    }

    const int ntiles = blockIdx.x + 17;   // last j tile touching i0+63+MLEN
    for (int t = 0; t < ntiles; t++) {
        const int j0 = t * 64;
        __syncthreads();   // protect sh_k/sh_v/sh_rk/sh_p from previous iteration

        // Load K (transposed [k][j]) and V ([j][d])
        for (int idx = tid; idx < 64 * 64; idx += 256) {
            int jj = idx >> 6, k = idx & 63;
            size_t base = (size_t)((j0 + jj) * BSZ + b) * (2 * DM) + n * DH + k;
            sh_k[k * 68 + jj] = kvb[base];
            sh_v[jj * 68 + k] = kvb[base + DM];
        }
        // Load rk window: rows dbase .. dbase+127, transposed [k][rr]
        const int dbase = j0 - i0 + (QLEN - 64);  // j0 - i0 + 960
        for (int idx = tid; idx < 128 * 64; idx += 256) {
            int rr = idx >> 6, k = idx & 63;
            int d = dbase + rr;
            float v = 0.f;
            if (d >= 0 && d < KLEN) v = rkb[(size_t)d * DM + n * DH + k];
            sh_rk[k * 132 + rr] = v;
        }
        __syncthreads();

        // ---- scores: AC + skewed BD ----
        float ac[4][4], bd[4][4];
#pragma unroll
        for (int i = 0; i < 4; i++)
#pragma unroll
            for (int j = 0; j < 4; j++) { ac[i][j] = 0.f; bd[i][j] = 0.f; }

        const int rel0 = jc - iw + 60;   // in [0,120]; thread needs rel0..rel0+6
#pragma unroll 4
        for (int k = 0; k < 64; k++) {
            float4 a4 = *(float4*)(sh_q  + k * 68  + iw);
            float4 b4 = *(float4*)(sh_k  + k * 68  + jc);
            float4 r0 = *(float4*)(sh_rk + k * 132 + rel0);
            float4 r1 = *(float4*)(sh_rk + k * 132 + rel0 + 4);
            float dk = sh_diff[k];
            float av[4] = {a4.x, a4.y, a4.z, a4.w};
            float bv[4] = {b4.x, b4.y, b4.z, b4.w};
            float rv[8] = {r0.x, r0.y, r0.z, r0.w, r1.x, r1.y, r1.z, r1.w};
#pragma unroll
            for (int ii = 0; ii < 4; ii++) {
                float ar = av[ii] + dk;
#pragma unroll
                for (int jj = 0; jj < 4; jj++) {
                    ac[ii][jj] += av[ii] * bv[jj];
                    bd[ii][jj] += ar * rv[jj - ii + 3];  // rel = (jc+jj)+63-(iw+ii)
                }
            }
        }

        // ---- mask, online softmax, write P^T ----
#pragma unroll
        for (int ii = 0; ii < 4; ii++) {
            const int ig = i0 + iw + ii;
            float s[4];
            float mx = -1e30f;
#pragma unroll
            for (int jj = 0; jj < 4; jj++) {
                int jg = j0 + jc + jj;
                float v = (ac[ii][jj] + bd[ii][jj]) * SCALE;
                if (jg > ig + MLEN) v = -1e30f;
                s[jj] = v;
                mx = fmaxf(mx, v);
            }
#pragma unroll
            for (int off = 8; off >= 1; off >>= 1)
                mx = fmaxf(mx, __shfl_xor_sync(0xffffffffu, mx, off));
            float mnew = fmaxf(m[ii], mx);
            float f = __expf(m[ii] - mnew);
            float rs = 0.f;
#pragma unroll
            for (int jj = 0; jj < 4; jj++) {
                float p = __expf(s[jj] - mnew);
                sh_p[(jc + jj) * 68 + iw + ii] = p;
                rs += p;
            }
#pragma unroll
            for (int off = 8; off >= 1; off >>= 1)
                rs += __shfl_xor_sync(0xffffffffu, rs, off);
            l[ii] = l[ii] * f + rs;
            m[ii] = mnew;
#pragma unroll
            for (int kk = 0; kk < 4; kk++) o[ii][kk] *= f;
        }
        __syncthreads();

        // ---- P @ V ----
#pragma unroll 4
        for (int j = 0; j < 64; j++) {
            float4 pa = *(float4*)(sh_p + j * 68 + iw);
            float4 vb = *(float4*)(sh_v + j * 68 + jc);
            float pv[4] = {pa.x, pa.y, pa.z, pa.w};
            float vv[4] = {vb.x, vb.y, vb.z, vb.w};
#pragma unroll
            for (int ii = 0; ii < 4; ii++)
#pragma unroll
                for (int kk = 0; kk < 4; kk++)
                    o[ii][kk] += pv[ii] * vv[kk];
        }
    }

    // ---- epilogue: normalize and write attn_vec ----
#pragma unroll
    for (int ii = 0; ii < 4; ii++) {
        float inv = 1.f / l[ii];
        float4 v = make_float4(o[ii][0] * inv, o[ii][1] * inv,
                               o[ii][2] * inv, o[ii][3] * inv);
        *(float4*)(vec + (size_t)((i0 + iw + ii) * BSZ + b) * DM + n * DH + jc) = v;
    }
}

// ---------------------------------------------------------------------------
// Residual + LayerNorm: out[row] = LN(w[row] + attn_out[row]) * g + b
// One CTA (256 threads) per row of 512.
// ---------------------------------------------------------------------------
__global__ __launch_bounds__(256) void ln_kernel(
    const float* __restrict__ w, const float* __restrict__ ao,
    const float* __restrict__ g, const float* __restrict__ bb,
    float* __restrict__ out)
{
    const int row = blockIdx.x;
    const int tid = threadIdx.x;
    const size_t base = (size_t)row * DM;

    float x0 = w[base + tid]       + ao[base + tid];
    float x1 = w[base + tid + 256] + ao[base + tid + 256];
    float s  = x0 + x1;
    float ss = x0 * x0 + x1 * x1;

#pragma unroll
    for (int off = 16; off >= 1; off >>= 1) {
        s  += __shfl_xor_sync(0xffffffffu, s,  off);
        ss += __shfl_xor_sync(0xffffffffu, ss, off);
    }
    __shared__ float sh_s[8], sh_ss[8];
    int wid = tid >> 5, lane = tid & 31;
    if (lane == 0) { sh_s[wid] = s; sh_ss[wid] = ss; }
    __syncthreads();
    if (tid == 0) {
        float a = 0.f, c = 0.f;
#pragma unroll
        for (int i = 0; i < 8; i++) { a += sh_s[i]; c += sh_ss[i]; }
        sh_s[0] = a; sh_ss[0] = c;
    }
    __syncthreads();

    float mean = sh_s[0] * (1.f / (float)DM);
    float var  = sh_ss[0] * (1.f / (float)DM) - mean * mean;
    float rstd = rsqrtf(var + LN_EPS);

    out[base + tid]       = (x0 - mean) * rstd * g[tid]       + bb[tid];
    out[base + tid + 256] = (x1 - mean) * rstd * g[tid + 256] + bb[tid + 256];
}

// ---------------------------------------------------------------------------
// Launcher
// ---------------------------------------------------------------------------
extern "C" void kernel_launch(void* const* d_in, const int* in_sizes, int n_in,
                              void* d_out, int out_size)
{
    const float* w    = (const float*)d_in[0];   // [1024,4,512]
    const float* r    = (const float*)d_in[1];   // [2048,1,512]
    const float* rwb  = (const float*)d_in[2];   // [8,64]
    const float* rrb  = (const float*)d_in[3];   // [8,64]
    const float* mems = (const float*)d_in[4];   // [1024,4,512]
    const float* Wq   = (const float*)d_in[5];   // [512,512]
    const float* Wkv  = (const float*)d_in[6];   // [512,1024]
    const float* Wr   = (const float*)d_in[7];   // [512,512]
    const float* Wo   = (const float*)d_in[8];   // [512,512]
    const float* lng  = (const float*)d_in[9];   // [512]
    const float* lnb  = (const float*)d_in[10];  // [512]
    // d_in[11] = attn_mask: computed analytically, unused.
    float* out = (float*)d_out;

    float *kv, *q, *rk, *vec, *ao;
    cudaGetSymbolAddress((void**)&kv,  g_kv);
    cudaGetSymbolAddress((void**)&q,   g_q);
    cudaGetSymbolAddress((void**)&rk,  g_rk);
    cudaGetSymbolAddress((void**)&vec, g_vec);
    cudaGetSymbolAddress((void**)&ao,  g_ao);

    // kv = cat(mems, w) @ Wkv  — cat flat rows = mems rows then w rows
    sgemm_k<<<dim3(1024 / BN, 4096 / BM), 256>>>(mems, Wkv, kv, 4096, 1024, 512);
    sgemm_k<<<dim3(1024 / BN, 4096 / BM), 256>>>(w, Wkv, kv + (size_t)4096 * 1024, 4096, 1024, 512);
    // q = w @ Wq
    sgemm_k<<<dim3(512 / BN, 4096 / BM), 256>>>(w, Wq, q, 4096, 512, 512);
    // rk = r @ Wr
    sgemm_k<<<dim3(512 / BN, 2048 / BM), 256>>>(r, Wr, rk, 2048, 512, 512);

    // fused attention
    cudaFuncSetAttribute(attn_kernel, cudaFuncAttributeMaxDynamicSharedMemorySize,
                         ATTN_SMEM_BYTES);
    attn_kernel<<<dim3(QLEN / 64, BSZ * NH), 256, ATTN_SMEM_BYTES>>>(q, kv, rk, rwb, rrb, vec);

    // attn_out = vec @ Wo
    sgemm_k<<<dim3(512 / BN, 4096 / BM), 256>>>(vec, Wo, ao, 4096, 512, 512);

    // residual + layernorm -> d_out
    ln_kernel<<<QLEN * BSZ, 256>>>(w, ao, lng, lnb, out);
}